// round 9
// baseline (speedup 1.0000x reference)
#include <cuda_runtime.h>

#define BB 1024
#define NN 64
#define DD 128
#define EE 512
#define NT (BB*NN)

// ---------------- scratch (device globals; allocation-free rule) ----------------
__device__ float g_dis[2][NT];
__device__ int   g_off[2][BB*65];
__device__ int   g_src[2][BB*EE];
__device__ float g_nrm[2][BB*EE];
__device__ float g_h[2][NT*DD];          // relu'd hidden per pass, updated in place
__device__ float g_sims[3][BB*64*64];    // [layer][graph][i(q)][j(c)]
__device__ float g_p1[3][BB*8*32*32];    // conv1+pool output
__device__ float g_feat[BB*12288];       // conv2+pool output, already in lin layout
__device__ float g_hidden[2][BB*512];    // k-split partial sums of linear layer

// ---------------- prep: per-graph degree + CSR (by dst) + norms ----------------
__global__ void __launch_bounds__(256) prep_kernel(const int* __restrict__ eiq,
                                                   const int* __restrict__ eic)
{
    int g = blockIdx.x;
    int p = blockIdx.y;
    const int* ei = p ? eic : eiq;
    __shared__ int   cnt[64];
    __shared__ int   cur[64];
    __shared__ float dsh[64];
    __shared__ int   soff[65];
    __shared__ short ls[EE], ldst[EE];
    int t = threadIdx.x;
    if (t < 64) cnt[t] = 0;
    __syncthreads();
    for (int e = t; e < EE; e += 256) {
        int s = ei[g*EE + e]          - g*NN;
        int d = ei[BB*EE + g*EE + e]  - g*NN;
        ls[e]   = (short)s;
        ldst[e] = (short)d;
        atomicAdd(&cnt[d], 1);
    }
    __syncthreads();
    if (t < 64) dsh[t] = rsqrtf((float)(cnt[t] + 1));   // +1 self loop
    __syncthreads();
    if (t == 0) {
        int acc = 0;
        for (int i = 0; i < 64; i++) { soff[i] = acc; acc += cnt[i]; }
        soff[64] = acc;
    }
    __syncthreads();
    if (t < 64) {
        cur[t] = soff[t];
        g_dis[p][g*NN + t]   = dsh[t];
        g_off[p][g*65 + t]   = soff[t];
    }
    if (t == 64) g_off[p][g*65 + 64] = soff[64];
    __syncthreads();
    for (int e = t; e < EE; e += 256) {
        int s = ls[e], d = ldst[e];
        int pos = atomicAdd(&cur[d], 1);
        g_src[p][g*EE + pos] = s;
        g_nrm[p][g*EE + pos] = dsh[s] * dsh[d];
    }
}

// ---------------- fused GCN layer (both passes) + similarity GEMM ----------------
// smem: W 64KB | h 32KB | m 32KB | out_q 32KB | out_c 32KB  = 192KB
__global__ void __launch_bounds__(256) gcn_kernel(int layer,
                                                  const float* __restrict__ xq,
                                                  const float* __restrict__ xc,
                                                  const float* __restrict__ w,
                                                  const float* __restrict__ bias)
{
    int g = blockIdx.x;
    int t = threadIdx.x;
    extern __shared__ float sm[];
    float* ws = sm;               // 128x128
    float* hs = ws + 16384;       // 64x128
    float* ms = hs + 8192;        // 64x128
    float* oq = ms + 8192;        // 64x128
    float* oc = oq + 8192;        // 64x128
    __shared__ float dis_s[64];
    __shared__ int   off_s[65];
    __shared__ float bias_s[128];

    for (int i = t; i < 4096; i += 256)
        ((float4*)ws)[i] = ((const float4*)w)[i];
    if (t < 128) bias_s[t] = bias[t];

    for (int p = 0; p < 2; p++) {
        const float* in   = (layer == 0) ? (p ? xc : xq) : g_h[p];
        float*       hout = g_h[p];
        const float* disp = g_dis[p] + g*NN;
        const int*   offp = g_off[p] + g*65;
        const int*   srcp = g_src[p] + g*EE;
        const float* nrmp = g_nrm[p] + g*EE;
        float*       ob   = p ? oc : oq;

        __syncthreads();
        {
            const float4* ip = (const float4*)(in + (size_t)g*NN*DD);
            for (int i = t; i < 2048; i += 256)
                ((float4*)hs)[i] = ip[i];
        }
        if (t < 64) dis_s[t] = disp[t];
        if (t >= 64 && t < 129) off_s[t-64] = offp[t-64];
        __syncthreads();

        // GEMM: ms(64x128) = hs(64x128) @ ws(128x128)
        {
            int c0 = (t & 31) * 4;
            int r0 = (t >> 5) * 8;
            float acc[8][4];
            #pragma unroll
            for (int r = 0; r < 8; r++) { acc[r][0]=0.f; acc[r][1]=0.f; acc[r][2]=0.f; acc[r][3]=0.f; }
            for (int k = 0; k < 128; k += 4) {
                float4 w0 = *(float4*)&ws[(k+0)*128 + c0];
                float4 w1 = *(float4*)&ws[(k+1)*128 + c0];
                float4 w2 = *(float4*)&ws[(k+2)*128 + c0];
                float4 w3 = *(float4*)&ws[(k+3)*128 + c0];
                #pragma unroll
                for (int r = 0; r < 8; r++) {
                    float4 hv = *(float4*)&hs[(r0+r)*128 + k];
                    acc[r][0] += hv.x*w0.x + hv.y*w1.x + hv.z*w2.x + hv.w*w3.x;
                    acc[r][1] += hv.x*w0.y + hv.y*w1.y + hv.z*w2.y + hv.w*w3.y;
                    acc[r][2] += hv.x*w0.z + hv.y*w1.z + hv.z*w2.z + hv.w*w3.z;
                    acc[r][3] += hv.x*w0.w + hv.y*w1.w + hv.z*w2.w + hv.w*w3.w;
                }
            }
            #pragma unroll
            for (int r = 0; r < 8; r++)
                *(float4*)&ms[(r0+r)*128 + c0] =
                    make_float4(acc[r][0], acc[r][1], acc[r][2], acc[r][3]);
        }
        __syncthreads();

        // CSR gather aggregation: out[d] = m[d]*dis[d]^2 + sum_in m[s]*dis[s]dis[d] + b
        {
            int f  = t & 127;
            int dh = t >> 7;
            float* houtg = hout + (size_t)g*NN*DD;
            #pragma unroll 1
            for (int di = 0; di < 32; di++) {
                int d = dh*32 + di;
                float dd = dis_s[d];
                float a = ms[d*128 + f] * dd * dd;
                int e1 = off_s[d+1];
                for (int e = off_s[d]; e < e1; e++) {
                    int s = srcp[e];
                    a += ms[s*128 + f] * nrmp[e];
                }
                float val = a + bias_s[f];
                ob[d*128 + f] = val;                       // pre-relu (for sims)
                houtg[d*128 + f] = fmaxf(val, 0.f);        // relu'd (next layer)
            }
        }
    }
    __syncthreads();

    // sims[i][j] = sum_k oq[i][k] * oc[j][k]
    {
        int j0 = (t & 15) * 4;
        int i0 = (t >> 4) * 4;
        float acc[4][4];
        #pragma unroll
        for (int r = 0; r < 4; r++)
            #pragma unroll
            for (int c = 0; c < 4; c++) acc[r][c] = 0.f;
        for (int k = 0; k < 128; k += 4) {
            float4 qa[4], cb[4];
            #pragma unroll
            for (int r = 0; r < 4; r++) qa[r] = *(float4*)&oq[(i0+r)*128 + k];
            #pragma unroll
            for (int c = 0; c < 4; c++) cb[c] = *(float4*)&oc[(j0+c)*128 + k];
            #pragma unroll
            for (int r = 0; r < 4; r++)
                #pragma unroll
                for (int c = 0; c < 4; c++)
                    acc[r][c] += qa[r].x*cb[c].x + qa[r].y*cb[c].y
                               + qa[r].z*cb[c].z + qa[r].w*cb[c].w;
        }
        float* so = g_sims[layer] + (size_t)g*4096;
        #pragma unroll
        for (int r = 0; r < 4; r++)
            *(float4*)&so[(i0+r)*64 + j0] =
                make_float4(acc[r][0], acc[r][1], acc[r][2], acc[r][3]);
    }
}

// ---------------- conv1 (1->8, 5x5, pad2) + relu + 2x2 maxpool ----------------
__global__ void __launch_bounds__(256) conv1_kernel(const float* __restrict__ w,
                                                    const float* __restrict__ b)
{
    int g = blockIdx.x, l = blockIdx.y, t = threadIdx.x;
    __shared__ float in_s[68*68];
    __shared__ float wsm[200];
    __shared__ float bsm[8];
    const float* simg = g_sims[l] + (size_t)g*4096;
    for (int idx = t; idx < 68*68; idx += 256) {
        int y = idx / 68, x = idx % 68;
        int iy = y - 2, ix = x - 2;
        float v = 0.f;
        if ((unsigned)iy < 64u && (unsigned)ix < 64u) v = simg[iy*64 + ix];
        in_s[idx] = v;
    }
    if (t < 200) wsm[t] = w[l*200 + t];
    if (t >= 200 && t < 208) bsm[t-200] = b[l*8 + (t-200)];
    __syncthreads();
    int c = t >> 5, px = t & 31;
    float wr[25];
    #pragma unroll
    for (int i = 0; i < 25; i++) wr[i] = wsm[c*25 + i];
    float bb = bsm[c];
    float* outp = g_p1[l] + ((size_t)g*8 + c)*1024;
    for (int py = 0; py < 32; py++) {
        float a0=0.f, a1=0.f, a2=0.f, a3=0.f;
        #pragma unroll
        for (int r = 0; r < 6; r++) {
            float v[6];
            #pragma unroll
            for (int q = 0; q < 6; q++) v[q] = in_s[(2*py + r)*68 + 2*px + q];
            if (r < 5) {
                #pragma unroll
                for (int dx = 0; dx < 5; dx++) {
                    float wv = wr[r*5+dx];
                    a0 += v[dx]*wv; a1 += v[dx+1]*wv;
                }
            }
            if (r >= 1) {
                #pragma unroll
                for (int dx = 0; dx < 5; dx++) {
                    float wv = wr[(r-1)*5+dx];
                    a2 += v[dx]*wv; a3 += v[dx+1]*wv;
                }
            }
        }
        float m = fmaxf(fmaxf(a0,a1), fmaxf(a2,a3));
        outp[py*32 + px] = fmaxf(m + bb, 0.f);
    }
}

// ---------------- conv2 (8->16, 5x5, pad2) + relu + 2x2 maxpool -> feat ----------------
__global__ void __launch_bounds__(256) conv2_kernel(const float* __restrict__ w,
                                                    const float* __restrict__ b)
{
    int g = blockIdx.x, l = blockIdx.y, t = threadIdx.x;
    extern __shared__ float sm2[];
    float* in_s = sm2;            // 8 x 36 x 36
    float* wsm  = in_s + 10368;   // 16 x 8 x 25
    float* bsm  = wsm + 3200;     // 16
    const float* p1g = g_p1[l] + (size_t)g*8192;
    for (int idx = t; idx < 10368; idx += 256) {
        int ic = idx / 1296, rem = idx % 1296;
        int y = rem / 36, x = rem % 36;
        int iy = y - 2, ix = x - 2;
        float v = 0.f;
        if ((unsigned)iy < 32u && (unsigned)ix < 32u) v = p1g[ic*1024 + iy*32 + ix];
        in_s[idx] = v;
    }
    for (int i = t; i < 3200; i += 256) wsm[i] = w[l*3200 + i];
    if (t < 16) bsm[t] = b[l*16 + t];
    __syncthreads();
    int c = t >> 4, py = t & 15;
    float acc0[32], acc1[32];
    #pragma unroll
    for (int i = 0; i < 32; i++) { acc0[i] = 0.f; acc1[i] = 0.f; }
    for (int ic = 0; ic < 8; ic++) {
        const float* wp = wsm + (c*8 + ic)*25;
        const float* ip = in_s + ic*1296;
        #pragma unroll
        for (int r = 0; r < 6; r++) {
            float v[36];
            const float* row = ip + (2*py + r)*36;
            #pragma unroll
            for (int q = 0; q < 36; q++) v[q] = row[q];
            if (r < 5) {
                #pragma unroll
                for (int dx = 0; dx < 5; dx++) {
                    float wv = wp[r*5+dx];
                    #pragma unroll
                    for (int ox = 0; ox < 32; ox++) acc0[ox] += v[ox+dx]*wv;
                }
            }
            if (r >= 1) {
                #pragma unroll
                for (int dx = 0; dx < 5; dx++) {
                    float wv = wp[(r-1)*5+dx];
                    #pragma unroll
                    for (int ox = 0; ox < 32; ox++) acc1[ox] += v[ox+dx]*wv;
                }
            }
        }
    }
    float bb = bsm[c];
    float* fo = g_feat + (size_t)g*12288 + (l*16 + c)*256 + py*16;
    #pragma unroll
    for (int px = 0; px < 16; px++) {
        float m = fmaxf(fmaxf(acc0[2*px], acc0[2*px+1]),
                        fmaxf(acc1[2*px], acc1[2*px+1]));
        fo[px] = fmaxf(m + bb, 0.f);
    }
}

// ---------------- linear (k-split x2): partial[z] = feat @ W[z-half] (+ bias on z=0) ----------------
__global__ void __launch_bounds__(256) lin_kernel(const float* __restrict__ W,
                                                  const float* __restrict__ bias)
{
    int bt = blockIdx.x * 64;
    int jt = blockIdx.y * 64;
    int z  = blockIdx.z;                 // k-half: [z*6144, (z+1)*6144)
    int t  = threadIdx.x;
    __shared__ float As[64*32];
    __shared__ float Bs[32*64];
    int j0 = (t & 15)*4, i0 = (t >> 4)*4;
    float acc[4][4];
    #pragma unroll
    for (int r = 0; r < 4; r++)
        #pragma unroll
        for (int c = 0; c < 4; c++) acc[r][c] = 0.f;
    int kbeg = z * 6144, kend = kbeg + 6144;
    for (int k0 = kbeg; k0 < kend; k0 += 32) {
        __syncthreads();
        #pragma unroll
        for (int q = 0; q < 2; q++) {
            int idx = t + q*256;
            int row = idx >> 3, col = (idx & 7)*4;
            ((float4*)As)[idx] = *(const float4*)&g_feat[(size_t)(bt+row)*12288 + k0 + col];
        }
        #pragma unroll
        for (int q = 0; q < 2; q++) {
            int idx = t + q*256;
            int kr = idx >> 4, col = (idx & 15)*4;
            ((float4*)Bs)[idx] = *(const float4*)&W[(size_t)(k0+kr)*512 + jt + col];
        }
        __syncthreads();
        #pragma unroll
        for (int k = 0; k < 32; k += 4) {
            float4 a4[4], b4[4];
            #pragma unroll
            for (int r = 0; r < 4; r++) a4[r] = *(float4*)&As[(i0+r)*32 + k];
            #pragma unroll
            for (int kk = 0; kk < 4; kk++) b4[kk] = *(float4*)&Bs[(k+kk)*64 + j0];
            #pragma unroll
            for (int r = 0; r < 4; r++) {
                acc[r][0] += a4[r].x*b4[0].x + a4[r].y*b4[1].x + a4[r].z*b4[2].x + a4[r].w*b4[3].x;
                acc[r][1] += a4[r].x*b4[0].y + a4[r].y*b4[1].y + a4[r].z*b4[2].y + a4[r].w*b4[3].y;
                acc[r][2] += a4[r].x*b4[0].z + a4[r].y*b4[1].z + a4[r].z*b4[2].z + a4[r].w*b4[3].z;
                acc[r][3] += a4[r].x*b4[0].w + a4[r].y*b4[1].w + a4[r].z*b4[2].w + a4[r].w*b4[3].w;
            }
        }
    }
    float* hz = g_hidden[z];
    #pragma unroll
    for (int r = 0; r < 4; r++)
        #pragma unroll
        for (int j = 0; j < 4; j++) {
            float v = acc[r][j];
            if (z == 0) v += bias[jt + j0 + j];
            hz[(size_t)(bt+i0+r)*512 + jt + j0 + j] = v;
        }
}

// ---------------- score: out[b] = score_b + sum_j relu(h0[b][j]+h1[b][j]) * score_w[j] ----------------
__global__ void __launch_bounds__(128) score_kernel(const float* __restrict__ sw,
                                                    const float* __restrict__ sb,
                                                    float* __restrict__ out)
{
    int b = blockIdx.x, t = threadIdx.x;
    __shared__ float red[128];
    float a = 0.f;
    for (int j = t; j < 512; j += 128) {
        float h = g_hidden[0][b*512 + j] + g_hidden[1][b*512 + j];
        a += fmaxf(h, 0.f) * sw[j];
    }
    red[t] = a;
    __syncthreads();
    for (int s = 64; s > 0; s >>= 1) {
        if (t < s) red[t] += red[t+s];
        __syncthreads();
    }
    if (t == 0) out[b] = red[0] + sb[0];
}

// ---------------- launcher ----------------
extern "C" void kernel_launch(void* const* d_in, const int* in_sizes, int n_in,
                              void* d_out, int out_size)
{
    const float* x_q = (const float*)d_in[0];
    const float* x_c = (const float*)d_in[1];
    const float* gw[3] = { (const float*)d_in[2], (const float*)d_in[4], (const float*)d_in[6] };
    const float* gb[3] = { (const float*)d_in[3], (const float*)d_in[5], (const float*)d_in[7] };
    const float* c1w = (const float*)d_in[8];
    const float* c1b = (const float*)d_in[9];
    const float* c2w = (const float*)d_in[10];
    const float* c2b = (const float*)d_in[11];
    const float* lw  = (const float*)d_in[12];
    const float* lb  = (const float*)d_in[13];
    const float* sw  = (const float*)d_in[14];
    const float* sb  = (const float*)d_in[15];
    const int*   eiq = (const int*)d_in[16];
    const int*   eic = (const int*)d_in[17];
    float* out = (float*)d_out;

    cudaFuncSetAttribute(gcn_kernel,  cudaFuncAttributeMaxDynamicSharedMemorySize, 196608);
    cudaFuncSetAttribute(conv2_kernel, cudaFuncAttributeMaxDynamicSharedMemorySize, 54336);

    prep_kernel<<<dim3(BB, 2), 256>>>(eiq, eic);
    for (int l = 0; l < 3; l++)
        gcn_kernel<<<BB, 256, 196608>>>(l, x_q, x_c, gw[l], gb[l]);
    conv1_kernel<<<dim3(BB, 3), 256>>>(c1w, c1b);
    conv2_kernel<<<dim3(BB, 3), 256, 54336>>>(c2w, c2b);
    lin_kernel<<<dim3(16, 8, 2), 256>>>(lw, lb);
    score_kernel<<<BB, 128>>>(sw, sb, out);
}

// round 13
// speedup vs baseline: 1.0958x; 1.0958x over previous
#include <cuda_runtime.h>

#define BB 1024
#define NN 64
#define DD 128
#define EE 512
#define NT (BB*NN)
#define KSPLIT 4

// ---------------- scratch (device globals; allocation-free rule) ----------------
__device__ float g_dis[2][NT];
__device__ int   g_off[2][BB*65];
__device__ int   g_src[2][BB*EE];
__device__ float g_nrm[2][BB*EE];
__device__ float g_h[2][NT*DD];          // relu'd hidden per pass, updated in place
__device__ float g_sims[3][BB*64*64];    // [layer][graph][i(q)][j(c)]
__device__ float g_p1[3][BB*8*32*32];    // conv1+pool output
__device__ float g_feat[BB*12288];       // conv2+pool output, already in lin layout
__device__ float g_hidden[KSPLIT][BB*512]; // k-split partial sums of linear layer

// ---------------- prep: per-graph degree + CSR (by dst) + norms ----------------
__global__ void __launch_bounds__(256) prep_kernel(const int* __restrict__ eiq,
                                                   const int* __restrict__ eic)
{
    int g = blockIdx.x;
    int p = blockIdx.y;
    const int* ei = p ? eic : eiq;
    __shared__ int   cnt[64];
    __shared__ int   cur[64];
    __shared__ float dsh[64];
    __shared__ int   soff[65];
    __shared__ short ls[EE], ldst[EE];
    int t = threadIdx.x;
    if (t < 64) cnt[t] = 0;
    __syncthreads();
    for (int e = t; e < EE; e += 256) {
        int s = ei[g*EE + e]          - g*NN;
        int d = ei[BB*EE + g*EE + e]  - g*NN;
        ls[e]   = (short)s;
        ldst[e] = (short)d;
        atomicAdd(&cnt[d], 1);
    }
    __syncthreads();
    if (t < 64) dsh[t] = rsqrtf((float)(cnt[t] + 1));   // +1 self loop
    __syncthreads();
    if (t == 0) {
        int acc = 0;
        for (int i = 0; i < 64; i++) { soff[i] = acc; acc += cnt[i]; }
        soff[64] = acc;
    }
    __syncthreads();
    if (t < 64) {
        cur[t] = soff[t];
        g_dis[p][g*NN + t]   = dsh[t];
        g_off[p][g*65 + t]   = soff[t];
    }
    if (t == 64) g_off[p][g*65 + 64] = soff[64];
    __syncthreads();
    for (int e = t; e < EE; e += 256) {
        int s = ls[e], d = ldst[e];
        int pos = atomicAdd(&cur[d], 1);
        g_src[p][g*EE + pos] = s;
        g_nrm[p][g*EE + pos] = dsh[s] * dsh[d];
    }
}

// ---------------- fused GCN layer (both passes) + similarity GEMM ----------------
// 512 threads (16 warps) for latency hiding; edges staged in static smem.
// dynamic smem: W 64KB | h 32KB | m 32KB | out_q 32KB | out_c 32KB = 192KB
__global__ void __launch_bounds__(512) gcn_kernel(int layer,
                                                  const float* __restrict__ xq,
                                                  const float* __restrict__ xc,
                                                  const float* __restrict__ w,
                                                  const float* __restrict__ bias)
{
    int g = blockIdx.x;
    int t = threadIdx.x;
    extern __shared__ float sm[];
    float* ws = sm;               // 128x128
    float* hs = ws + 16384;       // 64x128
    float* ms = hs + 8192;        // 64x128
    float* oq = ms + 8192;        // 64x128
    float* oc = oq + 8192;        // 64x128
    __shared__ float dis_s[64];
    __shared__ int   off_s[65];
    __shared__ float bias_s[128];
    __shared__ int   src_s[EE];
    __shared__ float nrm_s[EE];

    for (int i = t; i < 4096; i += 512)
        ((float4*)ws)[i] = ((const float4*)w)[i];
    if (t < 128) bias_s[t] = bias[t];

    for (int p = 0; p < 2; p++) {
        const float* in   = (layer == 0) ? (p ? xc : xq) : g_h[p];
        float*       hout = g_h[p];
        const float* disp = g_dis[p] + g*NN;
        const int*   offp = g_off[p] + g*65;
        const int*   srcp = g_src[p] + g*EE;
        const float* nrmp = g_nrm[p] + g*EE;
        float*       ob   = p ? oc : oq;

        __syncthreads();
        {
            const float4* ip = (const float4*)(in + (size_t)g*NN*DD);
            for (int i = t; i < 2048; i += 512)
                ((float4*)hs)[i] = ip[i];
        }
        if (t < 64) dis_s[t] = disp[t];
        if (t >= 64 && t < 129) off_s[t-64] = offp[t-64];
        if (t < EE) { src_s[t] = srcp[t]; nrm_s[t] = nrmp[t]; }
        __syncthreads();

        // GEMM: ms(64x128) = hs(64x128) @ ws(128x128); 16 warps x 4 rows
        {
            int c0 = (t & 31) * 4;
            int r0 = (t >> 5) * 4;
            float acc[4][4];
            #pragma unroll
            for (int r = 0; r < 4; r++) { acc[r][0]=0.f; acc[r][1]=0.f; acc[r][2]=0.f; acc[r][3]=0.f; }
            for (int k = 0; k < 128; k += 4) {
                float4 w0 = *(float4*)&ws[(k+0)*128 + c0];
                float4 w1 = *(float4*)&ws[(k+1)*128 + c0];
                float4 w2 = *(float4*)&ws[(k+2)*128 + c0];
                float4 w3 = *(float4*)&ws[(k+3)*128 + c0];
                #pragma unroll
                for (int r = 0; r < 4; r++) {
                    float4 hv = *(float4*)&hs[(r0+r)*128 + k];
                    acc[r][0] += hv.x*w0.x + hv.y*w1.x + hv.z*w2.x + hv.w*w3.x;
                    acc[r][1] += hv.x*w0.y + hv.y*w1.y + hv.z*w2.y + hv.w*w3.y;
                    acc[r][2] += hv.x*w0.z + hv.y*w1.z + hv.z*w2.z + hv.w*w3.z;
                    acc[r][3] += hv.x*w0.w + hv.y*w1.w + hv.z*w2.w + hv.w*w3.w;
                }
            }
            #pragma unroll
            for (int r = 0; r < 4; r++)
                *(float4*)&ms[(r0+r)*128 + c0] =
                    make_float4(acc[r][0], acc[r][1], acc[r][2], acc[r][3]);
        }
        __syncthreads();

        // CSR gather aggregation: out[d] = m[d]*dis[d]^2 + sum_in m[s]*dis[s]dis[d] + b
        // edges in smem -> LDS+LDS chain instead of LDG+LDS
        {
            int f  = t & 127;
            int dh = t >> 7;            // 0..3, 16 dsts each
            float* houtg = hout + (size_t)g*NN*DD;
            #pragma unroll 1
            for (int di = 0; di < 16; di++) {
                int d = dh*16 + di;
                float dd = dis_s[d];
                float a = ms[d*128 + f] * dd * dd;
                int e1 = off_s[d+1];
                for (int e = off_s[d]; e < e1; e++) {
                    int s = src_s[e];
                    a += ms[s*128 + f] * nrm_s[e];
                }
                float val = a + bias_s[f];
                ob[d*128 + f] = val;                       // pre-relu (for sims)
                houtg[d*128 + f] = fmaxf(val, 0.f);        // relu'd (next layer)
            }
        }
    }
    __syncthreads();

    // sims[i][j] = sum_k oq[i][k] * oc[j][k]; 512 threads: 2x4 tile each
    {
        int j0 = (t & 15) * 4;
        int i0 = (t >> 4) * 2;
        float acc[2][4];
        #pragma unroll
        for (int r = 0; r < 2; r++)
            #pragma unroll
            for (int c = 0; c < 4; c++) acc[r][c] = 0.f;
        for (int k = 0; k < 128; k += 4) {
            float4 qa[2], cb[4];
            #pragma unroll
            for (int r = 0; r < 2; r++) qa[r] = *(float4*)&oq[(i0+r)*128 + k];
            #pragma unroll
            for (int c = 0; c < 4; c++) cb[c] = *(float4*)&oc[(j0+c)*128 + k];
            #pragma unroll
            for (int r = 0; r < 2; r++)
                #pragma unroll
                for (int c = 0; c < 4; c++)
                    acc[r][c] += qa[r].x*cb[c].x + qa[r].y*cb[c].y
                               + qa[r].z*cb[c].z + qa[r].w*cb[c].w;
        }
        float* so = g_sims[layer] + (size_t)g*4096;
        #pragma unroll
        for (int r = 0; r < 2; r++)
            *(float4*)&so[(i0+r)*64 + j0] =
                make_float4(acc[r][0], acc[r][1], acc[r][2], acc[r][3]);
    }
}

// ---------------- conv1 (1->8, 5x5, pad2) + relu + 2x2 maxpool ----------------
__global__ void __launch_bounds__(256) conv1_kernel(const float* __restrict__ w,
                                                    const float* __restrict__ b)
{
    int g = blockIdx.x, l = blockIdx.y, t = threadIdx.x;
    __shared__ float in_s[68*68];
    __shared__ float wsm[200];
    __shared__ float bsm[8];
    const float* simg = g_sims[l] + (size_t)g*4096;
    for (int idx = t; idx < 68*68; idx += 256) {
        int y = idx / 68, x = idx % 68;
        int iy = y - 2, ix = x - 2;
        float v = 0.f;
        if ((unsigned)iy < 64u && (unsigned)ix < 64u) v = simg[iy*64 + ix];
        in_s[idx] = v;
    }
    if (t < 200) wsm[t] = w[l*200 + t];
    if (t >= 200 && t < 208) bsm[t-200] = b[l*8 + (t-200)];
    __syncthreads();
    int c = t >> 5, px = t & 31;
    float wr[25];
    #pragma unroll
    for (int i = 0; i < 25; i++) wr[i] = wsm[c*25 + i];
    float bb = bsm[c];
    float* outp = g_p1[l] + ((size_t)g*8 + c)*1024;
    for (int py = 0; py < 32; py++) {
        float a0=0.f, a1=0.f, a2=0.f, a3=0.f;
        #pragma unroll
        for (int r = 0; r < 6; r++) {
            float v[6];
            #pragma unroll
            for (int q = 0; q < 6; q++) v[q] = in_s[(2*py + r)*68 + 2*px + q];
            if (r < 5) {
                #pragma unroll
                for (int dx = 0; dx < 5; dx++) {
                    float wv = wr[r*5+dx];
                    a0 += v[dx]*wv; a1 += v[dx+1]*wv;
                }
            }
            if (r >= 1) {
                #pragma unroll
                for (int dx = 0; dx < 5; dx++) {
                    float wv = wr[(r-1)*5+dx];
                    a2 += v[dx]*wv; a3 += v[dx+1]*wv;
                }
            }
        }
        float m = fmaxf(fmaxf(a0,a1), fmaxf(a2,a3));
        outp[py*32 + px] = fmaxf(m + bb, 0.f);
    }
}

// ---------------- conv2 (8->16, 5x5, pad2) + relu + 2x2 maxpool -> feat ----------------
__global__ void __launch_bounds__(256) conv2_kernel(const float* __restrict__ w,
                                                    const float* __restrict__ b)
{
    int g = blockIdx.x, l = blockIdx.y, t = threadIdx.x;
    extern __shared__ float sm2[];
    float* in_s = sm2;            // 8 x 36 x 36
    float* wsm  = in_s + 10368;   // 16 x 8 x 25
    float* bsm  = wsm + 3200;     // 16
    const float* p1g = g_p1[l] + (size_t)g*8192;
    for (int idx = t; idx < 10368; idx += 256) {
        int ic = idx / 1296, rem = idx % 1296;
        int y = rem / 36, x = rem % 36;
        int iy = y - 2, ix = x - 2;
        float v = 0.f;
        if ((unsigned)iy < 32u && (unsigned)ix < 32u) v = p1g[ic*1024 + iy*32 + ix];
        in_s[idx] = v;
    }
    for (int i = t; i < 3200; i += 256) wsm[i] = w[l*3200 + i];
    if (t < 16) bsm[t] = b[l*16 + t];
    __syncthreads();
    int c = t >> 4, py = t & 15;
    float acc0[32], acc1[32];
    #pragma unroll
    for (int i = 0; i < 32; i++) { acc0[i] = 0.f; acc1[i] = 0.f; }
    for (int ic = 0; ic < 8; ic++) {
        const float* wp = wsm + (c*8 + ic)*25;
        const float* ip = in_s + ic*1296;
        #pragma unroll
        for (int r = 0; r < 6; r++) {
            float v[36];
            const float* row = ip + (2*py + r)*36;
            #pragma unroll
            for (int q = 0; q < 36; q++) v[q] = row[q];
            if (r < 5) {
                #pragma unroll
                for (int dx = 0; dx < 5; dx++) {
                    float wv = wp[r*5+dx];
                    #pragma unroll
                    for (int ox = 0; ox < 32; ox++) acc0[ox] += v[ox+dx]*wv;
                }
            }
            if (r >= 1) {
                #pragma unroll
                for (int dx = 0; dx < 5; dx++) {
                    float wv = wp[(r-1)*5+dx];
                    #pragma unroll
                    for (int ox = 0; ox < 32; ox++) acc1[ox] += v[ox+dx]*wv;
                }
            }
        }
    }
    float bb = bsm[c];
    float* fo = g_feat + (size_t)g*12288 + (l*16 + c)*256 + py*16;
    #pragma unroll
    for (int px = 0; px < 16; px++) {
        float m = fmaxf(fmaxf(acc0[2*px], acc0[2*px+1]),
                        fmaxf(acc1[2*px], acc1[2*px+1]));
        fo[px] = fmaxf(m + bb, 0.f);
    }
}

// ---------------- linear (k-split x4): partial[z] = feat @ W[z-quarter] (+ bias on z=0) ----------------
__global__ void __launch_bounds__(256) lin_kernel(const float* __restrict__ W,
                                                  const float* __restrict__ bias)
{
    int bt = blockIdx.x * 64;
    int jt = blockIdx.y * 64;
    int z  = blockIdx.z;                 // k-quarter: [z*3072, (z+1)*3072)
    int t  = threadIdx.x;
    __shared__ float As[64*32];
    __shared__ float Bs[32*64];
    int j0 = (t & 15)*4, i0 = (t >> 4)*4;
    float acc[4][4];
    #pragma unroll
    for (int r = 0; r < 4; r++)
        #pragma unroll
        for (int c = 0; c < 4; c++) acc[r][c] = 0.f;
    int kbeg = z * 3072, kend = kbeg + 3072;
    for (int k0 = kbeg; k0 < kend; k0 += 32) {
        __syncthreads();
        #pragma unroll
        for (int q = 0; q < 2; q++) {
            int idx = t + q*256;
            int row = idx >> 3, col = (idx & 7)*4;
            ((float4*)As)[idx] = *(const float4*)&g_feat[(size_t)(bt+row)*12288 + k0 + col];
        }
        #pragma unroll
        for (int q = 0; q < 2; q++) {
            int idx = t + q*256;
            int kr = idx >> 4, col = (idx & 15)*4;
            ((float4*)Bs)[idx] = *(const float4*)&W[(size_t)(k0+kr)*512 + jt + col];
        }
        __syncthreads();
        #pragma unroll
        for (int k = 0; k < 32; k += 4) {
            float4 a4[4], b4[4];
            #pragma unroll
            for (int r = 0; r < 4; r++) a4[r] = *(float4*)&As[(i0+r)*32 + k];
            #pragma unroll
            for (int kk = 0; kk < 4; kk++) b4[kk] = *(float4*)&Bs[(k+kk)*64 + j0];
            #pragma unroll
            for (int r = 0; r < 4; r++) {
                acc[r][0] += a4[r].x*b4[0].x + a4[r].y*b4[1].x + a4[r].z*b4[2].x + a4[r].w*b4[3].x;
                acc[r][1] += a4[r].x*b4[0].y + a4[r].y*b4[1].y + a4[r].z*b4[2].y + a4[r].w*b4[3].y;
                acc[r][2] += a4[r].x*b4[0].z + a4[r].y*b4[1].z + a4[r].z*b4[2].z + a4[r].w*b4[3].z;
                acc[r][3] += a4[r].x*b4[0].w + a4[r].y*b4[1].w + a4[r].z*b4[2].w + a4[r].w*b4[3].w;
            }
        }
    }
    float* hz = g_hidden[z];
    #pragma unroll
    for (int r = 0; r < 4; r++)
        #pragma unroll
        for (int j = 0; j < 4; j++) {
            float v = acc[r][j];
            if (z == 0) v += bias[jt + j0 + j];
            hz[(size_t)(bt+i0+r)*512 + jt + j0 + j] = v;
        }
}

// ---------------- score: out[b] = score_b + sum_j relu(sum_z hz[b][j]) * score_w[j] ----------------
__global__ void __launch_bounds__(128) score_kernel(const float* __restrict__ sw,
                                                    const float* __restrict__ sb,
                                                    float* __restrict__ out)
{
    int b = blockIdx.x, t = threadIdx.x;
    __shared__ float red[128];
    float a = 0.f;
    for (int j = t; j < 512; j += 128) {
        float h = g_hidden[0][b*512 + j] + g_hidden[1][b*512 + j]
                + g_hidden[2][b*512 + j] + g_hidden[3][b*512 + j];
        a += fmaxf(h, 0.f) * sw[j];
    }
    red[t] = a;
    __syncthreads();
    for (int s = 64; s > 0; s >>= 1) {
        if (t < s) red[t] += red[t+s];
        __syncthreads();
    }
    if (t == 0) out[b] = red[0] + sb[0];
}

// ---------------- launcher ----------------
extern "C" void kernel_launch(void* const* d_in, const int* in_sizes, int n_in,
                              void* d_out, int out_size)
{
    const float* x_q = (const float*)d_in[0];
    const float* x_c = (const float*)d_in[1];
    const float* gw[3] = { (const float*)d_in[2], (const float*)d_in[4], (const float*)d_in[6] };
    const float* gb[3] = { (const float*)d_in[3], (const float*)d_in[5], (const float*)d_in[7] };
    const float* c1w = (const float*)d_in[8];
    const float* c1b = (const float*)d_in[9];
    const float* c2w = (const float*)d_in[10];
    const float* c2b = (const float*)d_in[11];
    const float* lw  = (const float*)d_in[12];
    const float* lb  = (const float*)d_in[13];
    const float* sw  = (const float*)d_in[14];
    const float* sb  = (const float*)d_in[15];
    const int*   eiq = (const int*)d_in[16];
    const int*   eic = (const int*)d_in[17];
    float* out = (float*)d_out;

    cudaFuncSetAttribute(gcn_kernel,  cudaFuncAttributeMaxDynamicSharedMemorySize, 196608);
    cudaFuncSetAttribute(conv2_kernel, cudaFuncAttributeMaxDynamicSharedMemorySize, 54336);

    prep_kernel<<<dim3(BB, 2), 256>>>(eiq, eic);
    for (int l = 0; l < 3; l++)
        gcn_kernel<<<BB, 512, 196608>>>(l, x_q, x_c, gw[l], gb[l]);
    conv1_kernel<<<dim3(BB, 3), 256>>>(c1w, c1b);
    conv2_kernel<<<dim3(BB, 3), 256, 54336>>>(c2w, c2b);
    lin_kernel<<<dim3(16, 8, KSPLIT), 256>>>(lw, lb);
    score_kernel<<<BB, 128>>>(sw, sb, out);
}